// round 1
// baseline (speedup 1.0000x reference)
#include <cuda_runtime.h>
#include <math.h>

// Problem constants (from reference): B=2, S=2048 -> T=4096 tokens
#define NT 4096
#define HD 1024
#define FD 512
#define NE 8

// ---------------- device scratch (allocation-free) ----------------
__device__ int           g_cnt[NE];                       // tokens per expert
__device__ int           g_list[NE][NT];                  // token index per (expert, local row)
__device__ float         g_lw[NE][NT];                    // combine weight per (expert, local row)
__device__ unsigned char g_slot[NE][NT];                  // topk slot (0/1) per (expert, local row)
__device__ float         g_act[(size_t)NE * NT * FD];     // SwiGLU activations (64 MB)
__device__ float         g_part[(size_t)2 * NT * HD];     // per-slot down-proj partials (32 MB)

// ---------------- kernel 0: zero counters ----------------
__global__ void k_zero_cnt() {
    if (threadIdx.x < NE) g_cnt[threadIdx.x] = 0;
}

// ---------------- kernel 1: router (one warp per token) ----------------
__global__ void k_router(const float* __restrict__ x, const float* __restrict__ Wr) {
    int warp = (blockIdx.x * blockDim.x + threadIdx.x) >> 5;
    int lane = threadIdx.x & 31;
    if (warp >= NT) return;

    const float* xr = x + (size_t)warp * HD;
    float acc[NE];
#pragma unroll
    for (int e = 0; e < NE; e++) acc[e] = 0.f;

    for (int h = lane; h < HD; h += 32) {
        float xv = xr[h];
        const float* wrow = Wr + (size_t)h * NE;
#pragma unroll
        for (int e = 0; e < NE; e++) acc[e] += xv * wrow[e];
    }
#pragma unroll
    for (int off = 16; off > 0; off >>= 1) {
#pragma unroll
        for (int e = 0; e < NE; e++)
            acc[e] += __shfl_xor_sync(0xffffffffu, acc[e], off);
    }
    if (lane == 0) {
        // top-2 of logits (softmax is monotone; normalized top-k weights
        // reduce to a 2-way softmax over the top-2 logits)
        int i1 = 0;
#pragma unroll
        for (int e = 1; e < NE; e++) if (acc[e] > acc[i1]) i1 = e;
        int i2 = (i1 == 0) ? 1 : 0;
#pragma unroll
        for (int e = 0; e < NE; e++)
            if (e != i1 && acc[e] > acc[i2]) i2 = e;

        float w1 = 1.f / (1.f + expf(acc[i2] - acc[i1]));
        float w2 = 1.f - w1;

        int p1 = atomicAdd(&g_cnt[i1], 1);
        g_list[i1][p1] = warp; g_lw[i1][p1] = w1; g_slot[i1][p1] = 0;
        int p2 = atomicAdd(&g_cnt[i2], 1);
        g_list[i2][p2] = warp; g_lw[i2][p2] = w2; g_slot[i2][p2] = 1;
    }
}

// ---------------- kernel 2: fused gate/up GEMM + SwiGLU ----------------
// Per expert e: act[m, n] = silu(x_m . Wg_e[:, n]) * (x_m . Wu_e[:, n]) * w_m
// Tile: BM=64, BN=64, BK=16; 256 threads, 4x4 per thread, dual accumulators.
__global__ void k_gateup(const float* __restrict__ x,
                         const float* __restrict__ Wg,
                         const float* __restrict__ Wu) {
    int e   = blockIdx.z;
    int cnt = g_cnt[e];
    int m0  = blockIdx.x * 64;
    if (m0 >= cnt) return;
    int n0  = blockIdx.y * 64;

    __shared__ float As[64][16];
    __shared__ float Bg[16][64];
    __shared__ float Bu[16][64];
    __shared__ int   toks[64];

    int tid = threadIdx.x;
    if (tid < 64) {
        int r = m0 + tid;
        toks[tid] = (r < cnt) ? g_list[e][r] : 0;
    }
    __syncthreads();

    const float* wg = Wg + (size_t)e * HD * FD;
    const float* wu = Wu + (size_t)e * HD * FD;

    int ty = tid >> 4, tx = tid & 15;
    int arow = tid >> 2,  acol = (tid & 3) * 4;   // A tile load mapping
    int brow = tid >> 4,  bcol = (tid & 15) * 4;  // B tile load mapping

    float accg[4][4], accu[4][4];
#pragma unroll
    for (int i = 0; i < 4; i++)
#pragma unroll
        for (int j = 0; j < 4; j++) { accg[i][j] = 0.f; accu[i][j] = 0.f; }

    const float* aptr = x + (size_t)toks[arow] * HD + acol;

    for (int k0 = 0; k0 < HD; k0 += 16) {
        float4 av  = *(const float4*)(aptr + k0);
        float4 bgv = *(const float4*)(wg + (size_t)(k0 + brow) * FD + n0 + bcol);
        float4 buv = *(const float4*)(wu + (size_t)(k0 + brow) * FD + n0 + bcol);
        __syncthreads();
        *(float4*)&As[arow][acol] = av;
        *(float4*)&Bg[brow][bcol] = bgv;
        *(float4*)&Bu[brow][bcol] = buv;
        __syncthreads();
#pragma unroll
        for (int k = 0; k < 16; k++) {
            float a[4], bg4[4], bu4[4];
#pragma unroll
            for (int i = 0; i < 4; i++) a[i] = As[ty * 4 + i][k];
#pragma unroll
            for (int j = 0; j < 4; j++) { bg4[j] = Bg[k][tx * 4 + j]; bu4[j] = Bu[k][tx * 4 + j]; }
#pragma unroll
            for (int i = 0; i < 4; i++)
#pragma unroll
                for (int j = 0; j < 4; j++) {
                    accg[i][j] += a[i] * bg4[j];
                    accu[i][j] += a[i] * bu4[j];
                }
        }
    }

#pragma unroll
    for (int i = 0; i < 4; i++) {
        int r = m0 + ty * 4 + i;
        if (r >= cnt) continue;
        float w = g_lw[e][r];
        float* dst = g_act + ((size_t)e * NT + r) * FD + n0 + tx * 4;
#pragma unroll
        for (int j = 0; j < 4; j++) {
            float g = accg[i][j];
            float s = g / (1.f + __expf(-g));   // silu
            dst[j] = s * accu[i][j] * w;
        }
    }
}

// ---------------- kernel 3: down-proj GEMM, per-slot partials ----------------
// Per expert e: part[slot_r, tok_r, n] = act[r, :] . Wd_e[:, n]
__global__ void k_down(const float* __restrict__ Wd) {
    int e   = blockIdx.z;
    int cnt = g_cnt[e];
    int m0  = blockIdx.x * 64;
    if (m0 >= cnt) return;
    int n0  = blockIdx.y * 64;

    __shared__ float As[64][16];
    __shared__ float Bs[16][64];
    __shared__ int   toks[64];
    __shared__ int   slots[64];

    int tid = threadIdx.x;
    if (tid < 64) {
        int r = m0 + tid;
        toks[tid]  = (r < cnt) ? g_list[e][r] : 0;
        slots[tid] = (r < cnt) ? (int)g_slot[e][r] : 0;
    }
    __syncthreads();

    const float* wd = Wd + (size_t)e * FD * HD;
    const float* ab = g_act + ((size_t)e * NT + m0) * FD;

    int ty = tid >> 4, tx = tid & 15;
    int arow = tid >> 2,  acol = (tid & 3) * 4;
    int brow = tid >> 4,  bcol = (tid & 15) * 4;

    float acc[4][4];
#pragma unroll
    for (int i = 0; i < 4; i++)
#pragma unroll
        for (int j = 0; j < 4; j++) acc[i][j] = 0.f;

    for (int k0 = 0; k0 < FD; k0 += 16) {
        float4 av = *(const float4*)(ab + (size_t)arow * FD + k0 + acol);
        float4 bv = *(const float4*)(wd + (size_t)(k0 + brow) * HD + n0 + bcol);
        __syncthreads();
        *(float4*)&As[arow][acol] = av;
        *(float4*)&Bs[brow][bcol] = bv;
        __syncthreads();
#pragma unroll
        for (int k = 0; k < 16; k++) {
            float a[4], b4[4];
#pragma unroll
            for (int i = 0; i < 4; i++) a[i] = As[ty * 4 + i][k];
#pragma unroll
            for (int j = 0; j < 4; j++) b4[j] = Bs[k][tx * 4 + j];
#pragma unroll
            for (int i = 0; i < 4; i++)
#pragma unroll
                for (int j = 0; j < 4; j++)
                    acc[i][j] += a[i] * b4[j];
        }
    }

#pragma unroll
    for (int i = 0; i < 4; i++) {
        int r = m0 + ty * 4 + i;
        if (r >= cnt) continue;
        int t = toks[ty * 4 + i];
        int s = slots[ty * 4 + i];
        float* dst = g_part + ((size_t)s * NT + t) * HD + n0 + tx * 4;
#pragma unroll
        for (int j = 0; j < 4; j++) dst[j] = acc[i][j];
    }
}

// ---------------- kernel 4: combine slot partials -> output ----------------
__global__ void k_combine(float* __restrict__ out) {
    size_t i = ((size_t)blockIdx.x * blockDim.x + threadIdx.x) * 4;
    const size_t n = (size_t)NT * HD;
    if (i >= n) return;
    float4 a = *(const float4*)(g_part + i);
    float4 b = *(const float4*)(g_part + n + i);
    float4 o;
    o.x = a.x + b.x; o.y = a.y + b.y; o.z = a.z + b.z; o.w = a.w + b.w;
    *(float4*)(out + i) = o;
}

// ---------------- launch ----------------
extern "C" void kernel_launch(void* const* d_in, const int* in_sizes, int n_in,
                              void* d_out, int out_size) {
    const float* x  = (const float*)d_in[0];
    const float* Wr = (const float*)d_in[1];
    const float* Wg = (const float*)d_in[2];
    const float* Wu = (const float*)d_in[3];
    const float* Wd = (const float*)d_in[4];
    float* out = (float*)d_out;

    k_zero_cnt<<<1, 32>>>();
    k_router<<<NT / 8, 256>>>(x, Wr);                       // 8 warps/block
    k_gateup<<<dim3(NT / 64, FD / 64, NE), 256>>>(x, Wg, Wu);
    k_down  <<<dim3(NT / 64, HD / 64, NE), 256>>>(Wd);
    {
        size_t n4 = ((size_t)NT * HD) / 4;
        k_combine<<<(unsigned)((n4 + 255) / 256), 256>>>(out);
    }
}

// round 6
// speedup vs baseline: 1.8855x; 1.8855x over previous
#include <cuda_runtime.h>
#include <cstdint>
#include <math.h>

// Problem constants: B=2, S=2048 -> T=4096 tokens
#define NT 4096
#define HD 1024
#define FD 512
#define NE 8

#define BK 16
#define CH_GU (HD / BK)   // 64
#define CH_DN (FD / BK)   // 32

// ---------------- device scratch (allocation-free) ----------------
__device__ int           g_cnt[NE];
__device__ int           g_list[NE][NT];
__device__ float         g_lw[NE][NT];
__device__ unsigned char g_slot[NE][NT];
__device__ float         g_act[(size_t)NE * NT * FD];     // 64 MB
__device__ float         g_part[(size_t)2 * NT * HD];     // 32 MB

// ---------------- helpers ----------------
__device__ __forceinline__ uint32_t f2tf32(float x) {
    uint32_t r;
    asm("cvt.rna.tf32.f32 %0, %1;" : "=r"(r) : "f"(x));
    return r;
}
__device__ __forceinline__ void mma8(float* d, const uint32_t* a, const uint32_t* b) {
    asm volatile(
        "mma.sync.aligned.m16n8k8.row.col.f32.tf32.tf32.f32 "
        "{%0,%1,%2,%3}, {%4,%5,%6,%7}, {%8,%9}, {%0,%1,%2,%3};"
        : "+f"(d[0]), "+f"(d[1]), "+f"(d[2]), "+f"(d[3])
        : "r"(a[0]), "r"(a[1]), "r"(a[2]), "r"(a[3]), "r"(b[0]), "r"(b[1]));
}

// ---------------- kernel 0: zero counters ----------------
__global__ void k_zero_cnt() {
    if (threadIdx.x < NE) g_cnt[threadIdx.x] = 0;
}

// ---------------- kernel 1: router (one warp per token) ----------------
__global__ void k_router(const float* __restrict__ x, const float* __restrict__ Wr) {
    int warp = (blockIdx.x * blockDim.x + threadIdx.x) >> 5;
    int lane = threadIdx.x & 31;
    if (warp >= NT) return;

    const float* xr = x + (size_t)warp * HD;
    float acc[NE];
#pragma unroll
    for (int e = 0; e < NE; e++) acc[e] = 0.f;
    for (int h = lane; h < HD; h += 32) {
        float xv = xr[h];
        const float* wrow = Wr + (size_t)h * NE;
#pragma unroll
        for (int e = 0; e < NE; e++) acc[e] += xv * wrow[e];
    }
#pragma unroll
    for (int off = 16; off > 0; off >>= 1)
#pragma unroll
        for (int e = 0; e < NE; e++)
            acc[e] += __shfl_xor_sync(0xffffffffu, acc[e], off);
    if (lane == 0) {
        int i1 = 0;
#pragma unroll
        for (int e = 1; e < NE; e++) if (acc[e] > acc[i1]) i1 = e;
        int i2 = (i1 == 0) ? 1 : 0;
#pragma unroll
        for (int e = 0; e < NE; e++)
            if (e != i1 && acc[e] > acc[i2]) i2 = e;
        float w1 = 1.f / (1.f + expf(acc[i2] - acc[i1]));
        float w2 = 1.f - w1;
        int p1 = atomicAdd(&g_cnt[i1], 1);
        g_list[i1][p1] = warp; g_lw[i1][p1] = w1; g_slot[i1][p1] = 0;
        int p2 = atomicAdd(&g_cnt[i2], 1);
        g_list[i2][p2] = warp; g_lw[i2][p2] = w2; g_slot[i2][p2] = 1;
    }
}

// ---------------- kernel 2: gate/up HMMA GEMM + SwiGLU epilogue ----------------
// C[m,n]: gate = X.Wg_e, up = X.Wu_e over tile M=128 x N=64, K=HD.
// 8 warps: warpM = wid&3 (32 rows each), warpN = wid>>2 (32 cols each).
// A split hi/lo tf32 in registers (2 MMAs); B tf32-rounded at smem store.
__global__ __launch_bounds__(256) void k_gateup_mma(const float* __restrict__ x,
                                                    const float* __restrict__ Wg,
                                                    const float* __restrict__ Wu) {
    const int e   = blockIdx.z;
    const int cnt = g_cnt[e];
    const int m0  = blockIdx.x * 128;
    if (m0 >= cnt) return;
    const int n0  = blockIdx.y * 64;

    __shared__ float As[2][128][20];   // pad 20: conflict-free frag loads
    __shared__ float Bg[2][BK][72];    // pad 72
    __shared__ float Bu[2][BK][72];
    __shared__ int   toks[128];

    const int tid = threadIdx.x;
    const int wid = tid >> 5, lane = tid & 31;
    const int grp = lane >> 2, tig = lane & 3;
    const int wm = (wid & 3) * 32, wn = (wid >> 2) * 32;

    if (tid < 128) {
        int r = m0 + tid;
        toks[tid] = (r < cnt) ? g_list[e][r] : g_list[e][0];
    }
    __syncthreads();

    const float* wg = Wg + (size_t)e * HD * FD;
    const float* wu = Wu + (size_t)e * HD * FD;

    const int arow = tid >> 2, akq = (tid & 3) * 4;     // A: 2 iters of 64 rows
    const int brow = tid >> 4, bnq = (tid & 15) * 4;    // B: 16x64 in one pass
    const float* aptr0 = x + (size_t)toks[arow] * HD + akq;
    const float* aptr1 = x + (size_t)toks[arow + 64] * HD + akq;

    float4 rA0, rA1, rBg, rBu;
    auto fetch = [&](int c) {
        int k0 = c * BK;
        rA0 = *(const float4*)(aptr0 + k0);
        rA1 = *(const float4*)(aptr1 + k0);
        rBg = *(const float4*)(wg + (size_t)(k0 + brow) * FD + n0 + bnq);
        rBu = *(const float4*)(wu + (size_t)(k0 + brow) * FD + n0 + bnq);
    };
    auto store = [&](int st) {
        *(float4*)&As[st][arow][akq]      = rA0;
        *(float4*)&As[st][arow + 64][akq] = rA1;
        float4 bg, bu;
        bg.x = __uint_as_float(f2tf32(rBg.x)); bu.x = __uint_as_float(f2tf32(rBu.x));
        bg.y = __uint_as_float(f2tf32(rBg.y)); bu.y = __uint_as_float(f2tf32(rBu.y));
        bg.z = __uint_as_float(f2tf32(rBg.z)); bu.z = __uint_as_float(f2tf32(rBu.z));
        bg.w = __uint_as_float(f2tf32(rBg.w)); bu.w = __uint_as_float(f2tf32(rBu.w));
        *(float4*)&Bg[st][brow][bnq] = bg;
        *(float4*)&Bu[st][brow][bnq] = bu;
    };

    float dg[2][4][4], du[2][4][4];
#pragma unroll
    for (int i = 0; i < 2; i++)
#pragma unroll
        for (int j = 0; j < 4; j++)
#pragma unroll
            for (int q = 0; q < 4; q++) { dg[i][j][q] = 0.f; du[i][j][q] = 0.f; }

    fetch(0); store(0);
    __syncthreads();

    for (int c = 0; c < CH_GU; c++) {
        int st = c & 1;
        if (c + 1 < CH_GU) fetch(c + 1);
#pragma unroll
        for (int s = 0; s < 2; s++) {
            int kb = s * 8;
            uint32_t ah[2][4], al[2][4];
#pragma unroll
            for (int mt = 0; mt < 2; mt++) {
                int mB = wm + mt * 16 + grp;
                float a0 = As[st][mB][kb + tig];
                float a1 = As[st][mB + 8][kb + tig];
                float a2 = As[st][mB][kb + tig + 4];
                float a3 = As[st][mB + 8][kb + tig + 4];
                ah[mt][0] = f2tf32(a0); al[mt][0] = __float_as_uint(a0 - __uint_as_float(ah[mt][0]));
                ah[mt][1] = f2tf32(a1); al[mt][1] = __float_as_uint(a1 - __uint_as_float(ah[mt][1]));
                ah[mt][2] = f2tf32(a2); al[mt][2] = __float_as_uint(a2 - __uint_as_float(ah[mt][2]));
                ah[mt][3] = f2tf32(a3); al[mt][3] = __float_as_uint(a3 - __uint_as_float(ah[mt][3]));
            }
            uint32_t bg[4][2], bu[4][2];
#pragma unroll
            for (int nt = 0; nt < 4; nt++) {
                int nB = wn + nt * 8 + grp;
                bg[nt][0] = __float_as_uint(Bg[st][kb + tig][nB]);
                bg[nt][1] = __float_as_uint(Bg[st][kb + tig + 4][nB]);
                bu[nt][0] = __float_as_uint(Bu[st][kb + tig][nB]);
                bu[nt][1] = __float_as_uint(Bu[st][kb + tig + 4][nB]);
            }
#pragma unroll
            for (int mt = 0; mt < 2; mt++)
#pragma unroll
                for (int nt = 0; nt < 4; nt++) {
                    mma8(dg[mt][nt], ah[mt], bg[nt]);
                    mma8(dg[mt][nt], al[mt], bg[nt]);
                    mma8(du[mt][nt], ah[mt], bu[nt]);
                    mma8(du[mt][nt], al[mt], bu[nt]);
                }
        }
        __syncthreads();
        if (c + 1 < CH_GU) { store(st ^ 1); __syncthreads(); }
    }

    // epilogue: silu(gate)*up*w -> g_act
#pragma unroll
    for (int mt = 0; mt < 2; mt++) {
#pragma unroll
        for (int half = 0; half < 2; half++) {
            int r = wm + mt * 16 + grp + half * 8;
            int gr = m0 + r;
            if (gr >= cnt) continue;
            float w = g_lw[e][gr];
            float* orow = g_act + ((size_t)e * NT + gr) * FD + n0 + wn;
#pragma unroll
            for (int nt = 0; nt < 4; nt++) {
                float g0 = dg[mt][nt][half * 2 + 0], u0 = du[mt][nt][half * 2 + 0];
                float g1 = dg[mt][nt][half * 2 + 1], u1 = du[mt][nt][half * 2 + 1];
                float2 o;
                o.x = (g0 / (1.f + __expf(-g0))) * u0 * w;
                o.y = (g1 / (1.f + __expf(-g1))) * u1 * w;
                *(float2*)(orow + nt * 8 + tig * 2) = o;
            }
        }
    }
}

// ---------------- kernel 3: down-proj HMMA GEMM ----------------
// part[slot,tok,n] = act[r,:] . Wd_e[:,n]; tile M=128 x N=64, K=FD.
__global__ __launch_bounds__(256) void k_down_mma(const float* __restrict__ Wd) {
    const int e   = blockIdx.z;
    const int cnt = g_cnt[e];
    const int m0  = blockIdx.x * 128;
    if (m0 >= cnt) return;
    const int n0  = blockIdx.y * 64;

    __shared__ float As[2][128][20];
    __shared__ float Bs[2][BK][72];
    __shared__ int   toks[128];
    __shared__ int   slots[128];

    const int tid = threadIdx.x;
    const int wid = tid >> 5, lane = tid & 31;
    const int grp = lane >> 2, tig = lane & 3;
    const int wm = (wid & 3) * 32, wn = (wid >> 2) * 32;

    if (tid < 128) {
        int r = m0 + tid;
        toks[tid]  = (r < cnt) ? g_list[e][r] : 0;
        slots[tid] = (r < cnt) ? (int)g_slot[e][r] : 0;
    }
    __syncthreads();

    const float* wd = Wd + (size_t)e * FD * HD;
    const float* ab = g_act + ((size_t)e * NT + m0) * FD;

    const int arow = tid >> 2, akq = (tid & 3) * 4;
    const int brow = tid >> 4, bnq = (tid & 15) * 4;

    float4 rA0, rA1, rB;
    auto fetch = [&](int c) {
        int k0 = c * BK;
        rA0 = *(const float4*)(ab + (size_t)arow * FD + k0 + akq);
        rA1 = *(const float4*)(ab + (size_t)(arow + 64) * FD + k0 + akq);
        rB  = *(const float4*)(wd + (size_t)(k0 + brow) * HD + n0 + bnq);
    };
    auto store = [&](int st) {
        *(float4*)&As[st][arow][akq]      = rA0;
        *(float4*)&As[st][arow + 64][akq] = rA1;
        float4 b;
        b.x = __uint_as_float(f2tf32(rB.x));
        b.y = __uint_as_float(f2tf32(rB.y));
        b.z = __uint_as_float(f2tf32(rB.z));
        b.w = __uint_as_float(f2tf32(rB.w));
        *(float4*)&Bs[st][brow][bnq] = b;
    };

    float d[2][4][4];
#pragma unroll
    for (int i = 0; i < 2; i++)
#pragma unroll
        for (int j = 0; j < 4; j++)
#pragma unroll
            for (int q = 0; q < 4; q++) d[i][j][q] = 0.f;

    fetch(0); store(0);
    __syncthreads();

    for (int c = 0; c < CH_DN; c++) {
        int st = c & 1;
        if (c + 1 < CH_DN) fetch(c + 1);
#pragma unroll
        for (int s = 0; s < 2; s++) {
            int kb = s * 8;
            uint32_t ah[2][4], al[2][4];
#pragma unroll
            for (int mt = 0; mt < 2; mt++) {
                int mB = wm + mt * 16 + grp;
                float a0 = As[st][mB][kb + tig];
                float a1 = As[st][mB + 8][kb + tig];
                float a2 = As[st][mB][kb + tig + 4];
                float a3 = As[st][mB + 8][kb + tig + 4];
                ah[mt][0] = f2tf32(a0); al[mt][0] = __float_as_uint(a0 - __uint_as_float(ah[mt][0]));
                ah[mt][1] = f2tf32(a1); al[mt][1] = __float_as_uint(a1 - __uint_as_float(ah[mt][1]));
                ah[mt][2] = f2tf32(a2); al[mt][2] = __float_as_uint(a2 - __uint_as_float(ah[mt][2]));
                ah[mt][3] = f2tf32(a3); al[mt][3] = __float_as_uint(a3 - __uint_as_float(ah[mt][3]));
            }
            uint32_t b[4][2];
#pragma unroll
            for (int nt = 0; nt < 4; nt++) {
                int nB = wn + nt * 8 + grp;
                b[nt][0] = __float_as_uint(Bs[st][kb + tig][nB]);
                b[nt][1] = __float_as_uint(Bs[st][kb + tig + 4][nB]);
            }
#pragma unroll
            for (int mt = 0; mt < 2; mt++)
#pragma unroll
                for (int nt = 0; nt < 4; nt++) {
                    mma8(d[mt][nt], ah[mt], b[nt]);
                    mma8(d[mt][nt], al[mt], b[nt]);
                }
        }
        __syncthreads();
        if (c + 1 < CH_DN) { store(st ^ 1); __syncthreads(); }
    }

#pragma unroll
    for (int mt = 0; mt < 2; mt++) {
#pragma unroll
        for (int half = 0; half < 2; half++) {
            int r = wm + mt * 16 + grp + half * 8;
            int gr = m0 + r;
            if (gr >= cnt) continue;
            int tok = toks[r], sl = slots[r];
            float* dst = g_part + ((size_t)sl * NT + tok) * HD + n0 + wn;
#pragma unroll
            for (int nt = 0; nt < 4; nt++) {
                float2 o;
                o.x = d[mt][nt][half * 2 + 0];
                o.y = d[mt][nt][half * 2 + 1];
                *(float2*)(dst + nt * 8 + tig * 2) = o;
            }
        }
    }
}

// ---------------- kernel 4: combine slot partials -> output ----------------
__global__ void k_combine(float* __restrict__ out) {
    size_t i = ((size_t)blockIdx.x * blockDim.x + threadIdx.x) * 4;
    const size_t n = (size_t)NT * HD;
    if (i >= n) return;
    float4 a = *(const float4*)(g_part + i);
    float4 b = *(const float4*)(g_part + n + i);
    float4 o;
    o.x = a.x + b.x; o.y = a.y + b.y; o.z = a.z + b.z; o.w = a.w + b.w;
    *(float4*)(out + i) = o;
}

// ---------------- launch ----------------
extern "C" void kernel_launch(void* const* d_in, const int* in_sizes, int n_in,
                              void* d_out, int out_size) {
    const float* x  = (const float*)d_in[0];
    const float* Wr = (const float*)d_in[1];
    const float* Wg = (const float*)d_in[2];
    const float* Wu = (const float*)d_in[3];
    const float* Wd = (const float*)d_in[4];
    float* out = (float*)d_out;

    k_zero_cnt<<<1, 32>>>();
    k_router<<<NT / 8, 256>>>(x, Wr);
    k_gateup_mma<<<dim3(NT / 128, FD / 64, NE), 256>>>(x, Wg, Wu);
    k_down_mma  <<<dim3(NT / 128, HD / 64, NE), 256>>>(Wd);
    {
        size_t n4 = ((size_t)NT * HD) / 4;
        k_combine<<<(unsigned)((n4 + 255) / 256), 256>>>(out);
    }
}